// round 12
// baseline (speedup 1.0000x reference)
#include <cuda_runtime.h>
#include <cuda_bf16.h>

// Problem dims
#define B_   64
#define T_   96
#define F_   32
#define H_   128
#define HS4  512      // 4*H
#define NTH  512

// ---- shared memory layout (float offsets) ----
#define OFF_W1C    0        // 16384 f : w1 state rows bf16 [256][128] (enc/dec)
#define OFF_XDPRE  16384    // 6240 f  : decoder attn precompute bf16 [96][130] (65 uints/row)
                            //           encoder: xepre fp32 [32][136]
#define OFF_XM     22624    // 24576 f : decoder: XM deltas uint2[24][512] (paired rows)
                            //           encoder: xenc fp32 [96][129] @ +0, enc_k bf16 @ +12384
                            //           dec-pre: staged ad_w1 x-rows bf16 @ +12384
#define OFF_EKS    35008    // = OFF_XM + 12384 (enc_k bf16 during encoder)
#define OFF_XIN    47200    // 3072   : inputs[b] as [t][f]
#define OFF_RED4   50272    // 2048   : decoder B partials / encoder z / XM-stage tile
#define OFF_RED2   52320    // 1024   : encoder B partials 0,1
#define OFF_REDA   53344    // 1024   : a-partials 8x128 / e3[768]
#define OFF_ZS     54368    // 512    : decoder gate pre-activations / encoder B partial 2
#define OFF_MY     54880    // 512    : M row 128 (y coefficient)
#define OFF_BB     55392    // 512    : folded bias (dec) / enc_b cache (enc)
#define OFF_XMB    55904    // 512    : XM mean row (dec) / encoder B partial 3
#define OFF_HS     56416    // 256    : [h|s] / [d|c]
#define OFF_AW     56672    // 128
#define OFF_EW     56800    // 96
#define OFF_BETA   56896    // 96
#define OFF_XT     56992    // 32
#define OFF_CTX    57024    // 128
#define OFF_W2     57152    // 128
#define OFF_B1     57280    // 128
#define OFF_XSUM   57408    // 128
#define SMEM_F     57536
#define SMEM_BYTES (SMEM_F * 4)   // 230144 bytes

#define XE_S 129   // xenc fp32 row stride
#define XP_S 136   // xepre fp32 row stride (conflict-free with j=sub+8i mapping)
#define XD_U 65    // xdpre row stride in uints

#define BAR_A() asm volatile("bar.sync 1, 256;" ::: "memory")

// global scratch (static __device__ — no dynamic allocation)
__device__ float g_M[129 * 512];
__device__ float g_bb[512];
__device__ float g_xenc[B_ * T_ * H_];

// precise nonlinearities (LSTM cell only)
__device__ __forceinline__ float tanh_f(float x) {
    float e = __expf(2.0f * x);
    return 1.0f - __fdividef(2.0f, e + 1.0f);
}
__device__ __forceinline__ float sig_f(float x) {
    return __fdividef(1.0f, 1.0f + __expf(-x));
}
// fast tanh (attention only — softmax-damped)
__device__ __forceinline__ float tanh_a(float x) {
    float r;
    asm("tanh.approx.f32 %0, %1;" : "=f"(r) : "f"(x));
    return r;
}
__device__ __forceinline__ void fma4(float4& a, float s, const float4 w) {
    a.x = fmaf(s, w.x, a.x); a.y = fmaf(s, w.y, a.y);
    a.z = fmaf(s, w.z, a.z); a.w = fmaf(s, w.w, a.w);
}
// packed f32x2 helpers (FFMA2)
__device__ __forceinline__ unsigned long long pack2(float s) {
    unsigned long long r;
    asm("mov.b64 %0, {%1, %1};" : "=l"(r) : "f"(s));
    return r;
}
__device__ __forceinline__ void ffma2(unsigned long long& a, unsigned long long x,
                                      unsigned long long w) {
    asm("fma.rn.f32x2 %0, %1, %2, %0;" : "+l"(a) : "l"(x), "l"(w));
}
__device__ __forceinline__ float2 unpack2(unsigned long long a) {
    float2 f;
    asm("mov.b64 {%0, %1}, %2;" : "=f"(f.x), "=f"(f.y) : "l"(a));
    return f;
}
__device__ __forceinline__ float blo(unsigned u) { return __uint_as_float(u << 16); }
__device__ __forceinline__ float bhi(unsigned u) { return __uint_as_float(u & 0xffff0000u); }

extern __shared__ float sm[];

// ======  prep kernel: M = fc_w @ dec_k, folded bias  ======
__global__ void __launch_bounds__(512, 1)
prep_kernel(const float* __restrict__ fc_w, const float* __restrict__ fc_b,
            const float* __restrict__ dec_k, const float* __restrict__ dec_b)
{
    int col = threadIdx.x;
    int r = blockIdx.x;
    if (r < 129) {
        float acc = 0.f;
        #pragma unroll 8
        for (int j = 0; j < 128; ++j)
            acc = fmaf(fc_w[r * 128 + j], dec_k[j * 512 + col], acc);
        g_M[r * 512 + col] = acc;
    } else {
        float acc = dec_b[col];
        #pragma unroll 8
        for (int j = 0; j < 128; ++j)
            acc = fmaf(fc_b[j], dec_k[j * 512 + col], acc);
        g_bb[col] = acc;
    }
}

// fp32 recurrent matmul block (FFMA2): 4 parts x 32 rows x 8 cols per thread
__device__ __forceinline__ void zr_block_f32(const float* __restrict__ W,
                                             const float* hs, int th,
                                             float4& o0, float4& o1,
                                             int& colg_out, int& part_out)
{
    int colg = th & 63, part = th >> 6;
    int r0 = part * 32;
    unsigned long long a0 = 0ull, a1 = 0ull, a2 = 0ull, a3 = 0ull;
    #pragma unroll
    for (int c = 0; c < 8; ++c) {
        const int rb = r0 + c * 4;
        ulonglong2 w[8];
        #pragma unroll
        for (int k = 0; k < 4; ++k) {
            const ulonglong2* Wr = reinterpret_cast<const ulonglong2*>(W + (rb + k) * HS4);
            w[2 * k]     = Wr[2 * colg];
            w[2 * k + 1] = Wr[2 * colg + 1];
        }
        #pragma unroll
        for (int k = 0; k < 4; ++k) {
            unsigned long long sp = pack2(hs[rb + k]);
            ffma2(a0, sp, w[2 * k].x);     ffma2(a1, sp, w[2 * k].y);
            ffma2(a2, sp, w[2 * k + 1].x); ffma2(a3, sp, w[2 * k + 1].y);
        }
    }
    float2 f0 = unpack2(a0), f1 = unpack2(a1), f2 = unpack2(a2), f3 = unpack2(a3);
    o0 = make_float4(f0.x, f0.y, f1.x, f1.y);
    o1 = make_float4(f2.x, f2.y, f3.x, f3.y);
    colg_out = colg; part_out = part;
}

// =====================  main kernel  =====================
__global__ void __launch_bounds__(NTH, 1)
darnn_kernel(const float* __restrict__ inputs,
             const float* __restrict__ enc_k,
             const float* __restrict__ enc_r,
             const float* __restrict__ enc_b,
             const float* __restrict__ ae_w1, const float* __restrict__ ae_b1,
             const float* __restrict__ ae_w2,
             const float* __restrict__ dec_r,
             const float* __restrict__ ad_w1, const float* __restrict__ ad_b1,
             const float* __restrict__ ad_w2,
             const float* __restrict__ ff_w, const float* __restrict__ ff_b,
             float* __restrict__ out)
{
    const int tid = threadIdx.x;
    const int b   = blockIdx.x;

    __nv_bfloat16* w1c = (__nv_bfloat16*)(sm + OFF_W1C);
    const uint2*   w1c_u2 = (const uint2*)(sm + OFF_W1C);
    unsigned*      xdpre_u = (unsigned*)(sm + OFF_XDPRE);
    float*    xepre = sm + OFF_XDPRE;           // encoder alias of xdpre region
    float*    xmreg = sm + OFF_XM;              // encoder: xenc fp32 at base
    __nv_bfloat16* eks = (__nv_bfloat16*)(sm + OFF_EKS);    // encoder: enc_k bf16
    __nv_bfloat16* w1x = (__nv_bfloat16*)(sm + OFF_XM + 12384);  // dec-pre staging
    const uint2*   w1x_u2 = (const uint2*)(sm + OFF_XM + 12384);
    unsigned* XM_u  = (unsigned*)(sm + OFF_XM); // decoder: paired bf16x2 deltas
    float* xin   = sm + OFF_XIN;
    float* red4  = sm + OFF_RED4;
    float* red2  = sm + OFF_RED2;
    float* redA  = sm + OFF_REDA;
    float* e3    = sm + OFF_REDA;               // decoder e-partials (aliases redA)
    float* zs    = sm + OFF_ZS;
    float* my    = sm + OFF_MY;
    float* bbs   = sm + OFF_BB;
    float* xmb   = sm + OFF_XMB;
    float* hs    = sm + OFF_HS;
    float* aw    = sm + OFF_AW;
    float* ew    = sm + OFF_EW;
    float* beta  = sm + OFF_BETA;
    float* xt    = sm + OFF_XT;
    float* ctx   = sm + OFF_CTX;
    float* w2c   = sm + OFF_W2;
    float* b1c   = sm + OFF_B1;
    float* xsum  = sm + OFF_XSUM;

    // ---------- Phase 0: stage inputs + encoder constants ----------
    for (int i = tid; i < T_ * F_; i += NTH) xin[i] = inputs[b * T_ * F_ + i];
    for (int i = tid; i < 256 * H_; i += NTH) w1c[i] = __float2bfloat16_rn(ae_w1[i]);
    for (int i = tid; i < F_ * HS4; i += NTH) eks[i] = __float2bfloat16_rn(enc_k[i]);
    if (tid < H_)   { w2c[tid] = ae_w2[tid]; b1c[tid] = ae_b1[tid]; }
    if (tid < 2*H_) hs[tid] = 0.0f;
    for (int i = tid; i < HS4; i += NTH) bbs[i] = enc_b[i];
    __syncthreads();

    // xe_pre[f][j] = sum_t x[t][f] * ae_w1[2H+t][j]  (one-time hoist)
    for (int slot = tid; slot < F_ * (H_ / 4); slot += NTH) {
        int f = slot >> 5, jq = slot & 31;
        float4 acc = make_float4(0.f, 0.f, 0.f, 0.f);
        #pragma unroll 4
        for (int t = 0; t < T_; ++t) {
            float xv = xin[t * F_ + f];
            float4 w = reinterpret_cast<const float4*>(ae_w1 + (256 + t) * H_)[jq];
            fma4(acc, xv, w);
        }
        float* dst = xepre + f * XP_S + jq * 4;
        dst[0] = acc.x; dst[1] = acc.y; dst[2] = acc.z; dst[3] = acc.w;
    }
    __syncthreads();

    // ---------- Phase 1: encoder (96 steps, overlapped groups) ----------
    for (int t = 0; t < T_; ++t) {
        if (tid < 256) {
            // Group A: a-partials [h|s]@w1 (bf16), 8 parts x 32 rows x 4 cols
            {
                int cg = tid & 31, part = tid >> 5;
                float a0 = 0.f, a1 = 0.f, a2 = 0.f, a3 = 0.f;
                int r0 = part * 32;
                #pragma unroll 8
                for (int r = r0; r < r0 + 32; ++r) {
                    float s = hs[r];
                    uint2 w = w1c_u2[r * 32 + cg];
                    a0 = fmaf(s, blo(w.x), a0); a1 = fmaf(s, bhi(w.x), a1);
                    a2 = fmaf(s, blo(w.y), a2); a3 = fmaf(s, bhi(w.y), a3);
                }
                reinterpret_cast<float4*>(redA + part * H_ + cg * 4)[0] =
                    make_float4(a0, a1, a2, a3);
            }
            BAR_A();
            if (tid < H_) {
                float acc = b1c[tid];
                #pragma unroll
                for (int p = 0; p < 8; ++p) acc += redA[p * H_ + tid];
                aw[tid] = acc;
            }
            BAR_A();
            // e[f] = sum_j tanh(xe_pre + a) * w2  (8 thr/f, interleaved j)
            {
                int f = tid >> 3, sub = tid & 7;
                float acc = 0.f;
                #pragma unroll
                for (int i = 0; i < 16; ++i) {
                    int j = sub + 8 * i;
                    acc += tanh_a(xepre[f * XP_S + j] + aw[j]) * w2c[j];
                }
                acc += __shfl_down_sync(0xffffffffu, acc, 4);
                acc += __shfl_down_sync(0xffffffffu, acc, 2);
                acc += __shfl_down_sync(0xffffffffu, acc, 1);
                if (sub == 0) ew[f] = acc;
            }
            BAR_A();
            // softmax over F=32 -> x_tilde
            if (tid < 32) {
                float v = ew[tid], m = v;
                #pragma unroll
                for (int o = 16; o; o >>= 1) m = fmaxf(m, __shfl_xor_sync(0xffffffffu, m, o));
                float p = __expf(v - m), s = p;
                #pragma unroll
                for (int o = 16; o; o >>= 1) s += __shfl_xor_sync(0xffffffffu, s, o);
                xt[tid] = __fdividef(p, s) * xin[t * F_ + tid];
            }
        } else {
            // Group B: zr = h @ enc_r (fp32 FFMA2), 4 parts x 32 rows x 8 cols
            float4 o0, o1; int colg, part;
            zr_block_f32(enc_r, hs, tid - 256, o0, o1, colg, part);
            float* dst = (part == 0) ? red2 : (part == 1) ? (red2 + 512)
                       : (part == 2) ? zs : xmb;
            reinterpret_cast<float4*>(dst + colg * 8)[0]     = o0;
            reinterpret_cast<float4*>(dst + colg * 8 + 4)[0] = o1;
        }
        __syncthreads();

        // z-combine (512 thr, 1 col): bias + 4 zr parts + x_tilde @ enc_k (smem bf16)
        {
            int col = tid;
            float z = bbs[col] + red2[col] + red2[512 + col] + zs[col] + xmb[col];
            #pragma unroll 8
            for (int r = 0; r < 32; ++r)
                z = fmaf(xt[r], __bfloat162float(eks[r * HS4 + col]), z);
            red4[col] = z;
        }
        __syncthreads();

        // LSTM cell
        if (tid < H_) {
            int j = tid;
            float ig = sig_f(red4[j]), fg = sig_f(red4[H_ + j]);
            float gg = tanh_f(red4[2 * H_ + j]), og = sig_f(red4[3 * H_ + j]);
            float c = fg * hs[H_ + j] + ig * gg;
            float h = og * tanh_f(c);
            hs[j] = h; hs[H_ + j] = c;
            xmreg[t * XE_S + j] = h;
            g_xenc[(b * T_ + t) * H_ + j] = h;
        }
        __syncthreads();
    }

    // ---------- Phase 2: decoder precomputes ----------
    for (int i = tid; i < 256 * H_; i += NTH) w1c[i] = __float2bfloat16_rn(ad_w1[i]);
    for (int i = tid; i < H_ * H_; i += NTH)
        w1x[i] = __float2bfloat16_rn(ad_w1[256 * H_ + i]);
    if (tid < H_)   { w2c[tid] = ad_w2[tid]; b1c[tid] = ad_b1[tid]; }
    if (tid < 2*H_) hs[tid] = 0.0f;
    if (tid < 512)  { bbs[tid] = g_bb[tid]; my[tid] = g_M[128 * 512 + tid]; }
    __syncthreads();

    // xd_pre[tt][j] -> bf16 [96][130]
    for (int slot = tid; slot < T_ * (H_ / 4); slot += NTH) {
        int tt = slot >> 5, jq = slot & 31;
        float a0 = 0.f, a1 = 0.f, a2 = 0.f, a3 = 0.f;
        #pragma unroll 8
        for (int k = 0; k < H_; ++k) {
            float xv = xmreg[tt * XE_S + k];
            uint2 w = w1x_u2[k * 32 + jq];
            a0 = fmaf(xv, blo(w.x), a0); a1 = fmaf(xv, bhi(w.x), a1);
            a2 = fmaf(xv, blo(w.y), a2); a3 = fmaf(xv, bhi(w.y), a3);
        }
        __nv_bfloat162 h0 = __floats2bfloat162_rn(a0, a1);
        __nv_bfloat162 h1 = __floats2bfloat162_rn(a2, a3);
        xdpre_u[tt * XD_U + jq * 2]     = *reinterpret_cast<unsigned*>(&h0);
        xdpre_u[tt * XD_U + jq * 2 + 1] = *reinterpret_cast<unsigned*>(&h1);
    }
    // xsum[k] = sum_tt xenc[tt][k]
    if (tid < H_) {
        float acc = 0.f;
        #pragma unroll 8
        for (int tt = 0; tt < T_; ++tt) acc += xmreg[tt * XE_S + tid];
        xsum[tid] = acc;
    }
    __syncthreads();

    // XMbar[col] = (1/96) * sum_k xsum[k] * M[k][col]
    {
        int col = tid;
        float acc = 0.f;
        #pragma unroll 8
        for (int k = 0; k < H_; ++k)
            acc = fmaf(xsum[k], g_M[k * 512 + col], acc);
        xmb[col] = acc * (1.0f / 96.0f);
    }
    __syncthreads();

    // XM passes, reverse order p=5..0 (writes stay ahead of later xenc reads)
    // New layout: XM_u as uint2 rows q2=0..23, row stride 1024 uints (512 uint2),
    // row q2 covers tt 4*q2..4*q2+3.
    for (int p = 5; p >= 0; --p) {
        for (int idx = tid; idx < 2048; idx += NTH) {
            int k = idx >> 4, u = idx & 15;
            red4[idx] = xmreg[(16 * p + u) * XE_S + k];
        }
        __syncthreads();
        {
            int col = tid;
            unsigned long long acc2[8];
            #pragma unroll
            for (int j = 0; j < 8; ++j) acc2[j] = 0ull;
            const float* Mp = g_M + col;
            const ulonglong2* Tb = (const ulonglong2*)red4;
            #pragma unroll 4
            for (int k = 0; k < 128; ++k) {
                unsigned long long mm = pack2(Mp[k * 512]);
                ulonglong2 t0 = Tb[k * 4 + 0];
                ulonglong2 t1 = Tb[k * 4 + 1];
                ulonglong2 t2 = Tb[k * 4 + 2];
                ulonglong2 t3 = Tb[k * 4 + 3];
                ffma2(acc2[0], t0.x, mm); ffma2(acc2[1], t0.y, mm);
                ffma2(acc2[2], t1.x, mm); ffma2(acc2[3], t1.y, mm);
                ffma2(acc2[4], t2.x, mm); ffma2(acc2[5], t2.y, mm);
                ffma2(acc2[6], t3.x, mm); ffma2(acc2[7], t3.y, mm);
            }
            float xb = xmb[col];
            #pragma unroll
            for (int j2 = 0; j2 < 4; ++j2) {
                float2 fa = unpack2(acc2[2 * j2]);
                float2 fb = unpack2(acc2[2 * j2 + 1]);
                __nv_bfloat162 ha = __floats2bfloat162_rn(fa.x - xb, fa.y - xb);
                __nv_bfloat162 hb = __floats2bfloat162_rn(fb.x - xb, fb.y - xb);
                uint2 v;
                v.x = *reinterpret_cast<unsigned*>(&ha);
                v.y = *reinterpret_cast<unsigned*>(&hb);
                *reinterpret_cast<uint2*>(XM_u + (4 * p + j2) * 1024 + col * 2) = v;
            }
        }
        __syncthreads();
    }

    // ---------- Phase 3: decoder (96 steps) ----------
    for (int t = 0; t < T_; ++t) {
        if (tid < 256) {
            // ===== Group A: full attention chain (overlaps B) =====
            {
                int cg = tid & 31, part = tid >> 5;
                float a0 = 0.f, a1 = 0.f, a2 = 0.f, a3 = 0.f;
                int r0 = part * 32;
                #pragma unroll 8
                for (int r = r0; r < r0 + 32; ++r) {
                    float s = hs[r];
                    uint2 w = w1c_u2[r * 32 + cg];
                    a0 = fmaf(s, blo(w.x), a0); a1 = fmaf(s, bhi(w.x), a1);
                    a2 = fmaf(s, blo(w.y), a2); a3 = fmaf(s, bhi(w.y), a3);
                }
                reinterpret_cast<float4*>(redA + part * H_ + cg * 4)[0] =
                    make_float4(a0, a1, a2, a3);
            }
            BAR_A();
            if (tid < H_) {
                float acc = b1c[tid];
                #pragma unroll
                for (int p = 0; p < 8; ++p) acc += redA[p * H_ + tid];
                aw[tid] = acc;
            }
            BAR_A();
            // e-phase on 256 threads: 3 units x 16 tanh (unit = jb*96+tt)
            {
                #pragma unroll
                for (int k2 = 0; k2 < 3; ++k2) {
                    int unit = tid + 256 * k2;
                    int tt = unit % 96, jb = unit / 96;
                    const unsigned* row = xdpre_u + tt * XD_U + jb * 8;
                    int j0 = jb * 16;
                    float acc = 0.f;
                    #pragma unroll
                    for (int i = 0; i < 8; ++i) {
                        unsigned u = row[i];
                        int j = j0 + 2 * i;
                        acc += tanh_a(blo(u) + aw[j])     * w2c[j];
                        acc += tanh_a(bhi(u) + aw[j + 1]) * w2c[j + 1];
                    }
                    e3[unit] = acc;
                }
            }
            BAR_A();
            // softmax over T=96 (sum 8 jb-partials per tt)
            if (tid < 32) {
                float v0 = 0.f, v1 = 0.f, v2 = 0.f;
                #pragma unroll
                for (int jb = 0; jb < 8; ++jb) {
                    v0 += e3[jb * 96 + tid];
                    v1 += e3[jb * 96 + tid + 32];
                    v2 += e3[jb * 96 + tid + 64];
                }
                float m = fmaxf(v0, fmaxf(v1, v2));
                #pragma unroll
                for (int o = 16; o; o >>= 1) m = fmaxf(m, __shfl_xor_sync(0xffffffffu, m, o));
                float p0 = __expf(v0 - m), p1 = __expf(v1 - m), p2 = __expf(v2 - m);
                float s = p0 + p1 + p2;
                #pragma unroll
                for (int o = 16; o; o >>= 1) s += __shfl_xor_sync(0xffffffffu, s, o);
                float inv = __fdividef(1.0f, s);
                beta[tid] = p0 * inv; beta[tid + 32] = p1 * inv; beta[tid + 64] = p2 * inv;
            }
        } else {
            // ===== Group B: zr = d @ dec_r (fp32 FFMA2), 4 parts x 32 rows =====
            float4 o0, o1; int colg, part;
            zr_block_f32(dec_r, hs, tid - 256, o0, o1, colg, part);
            float* dst = red4 + part * HS4;
            reinterpret_cast<float4*>(dst + colg * 8)[0]     = o0;
            reinterpret_cast<float4*>(dst + colg * 8 + 4)[0] = o1;
        }
        __syncthreads();

        // z[col] = bb + sum(zr parts) + y*my + XMbar + sum_q2 beta4·XMdelta
        {
            int col = tid;
            float z = bbs[col] + xmb[col];
            z += red4[col] + red4[512 + col] + red4[1024 + col] + red4[1536 + col];
            z = fmaf(xin[t * F_ + (F_ - 1)], my[col], z);
            const uint2* xr = reinterpret_cast<const uint2*>(XM_u) + col;
            const float4* b4 = reinterpret_cast<const float4*>(beta);
            #pragma unroll 8
            for (int q2 = 0; q2 < 24; ++q2) {
                uint2 u = xr[q2 * 512];
                float4 bq = b4[q2];
                z = fmaf(bq.x, blo(u.x), z);
                z = fmaf(bq.y, bhi(u.x), z);
                z = fmaf(bq.z, blo(u.y), z);
                z = fmaf(bq.w, bhi(u.y), z);
            }
            zs[col] = z;
        }
        __syncthreads();

        // LSTM cell
        if (tid < H_) {
            int j = tid;
            float ig = sig_f(zs[j]), fg = sig_f(zs[H_ + j]);
            float gg = tanh_f(zs[2 * H_ + j]), og = sig_f(zs[3 * H_ + j]);
            float c = fg * hs[H_ + j] + ig * gg;
            float d = og * tanh_f(c);
            hs[j] = d; hs[H_ + j] = c;
        }
        __syncthreads();
    }

    // ---------- Phase 4: final ctx + output head ----------
    if (tid < H_) {
        float acc = 0.f;
        const float* xg = g_xenc + b * T_ * H_ + tid;
        #pragma unroll 8
        for (int tt = 0; tt < T_; ++tt) acc += beta[tt] * xg[tt * H_];
        ctx[tid] = acc;
    }
    __syncthreads();
    if (tid < F_) {
        float acc = ff_b[tid];
        #pragma unroll 4
        for (int k = 0; k < H_; ++k) acc += hs[k] * ff_w[k * F_ + tid];
        #pragma unroll 4
        for (int k = 0; k < H_; ++k) acc += ctx[k] * ff_w[(H_ + k) * F_ + tid];
        out[b * F_ + tid] = acc;
    }
}

extern "C" void kernel_launch(void* const* d_in, const int* in_sizes, int n_in,
                              void* d_out, int out_size) {
    const float* inputs = (const float*)d_in[0];
    const float* enc_k  = (const float*)d_in[1];
    const float* enc_r  = (const float*)d_in[2];
    const float* enc_b  = (const float*)d_in[3];
    const float* ae_w1  = (const float*)d_in[4];
    const float* ae_b1  = (const float*)d_in[5];
    const float* ae_w2  = (const float*)d_in[6];
    const float* dec_k  = (const float*)d_in[8];
    const float* dec_r  = (const float*)d_in[9];
    const float* dec_b  = (const float*)d_in[10];
    const float* ad_w1  = (const float*)d_in[11];
    const float* ad_b1  = (const float*)d_in[12];
    const float* ad_w2  = (const float*)d_in[13];
    const float* fc_w   = (const float*)d_in[15];
    const float* fc_b   = (const float*)d_in[16];
    const float* ff_w   = (const float*)d_in[17];
    const float* ff_b   = (const float*)d_in[18];
    float* out = (float*)d_out;

    prep_kernel<<<130, 512>>>(fc_w, fc_b, dec_k, dec_b);

    cudaFuncSetAttribute(darnn_kernel, cudaFuncAttributeMaxDynamicSharedMemorySize, SMEM_BYTES);
    darnn_kernel<<<B_, NTH, SMEM_BYTES>>>(inputs, enc_k, enc_r, enc_b,
                                          ae_w1, ae_b1, ae_w2,
                                          dec_r,
                                          ad_w1, ad_b1, ad_w2,
                                          ff_w, ff_b, out);
}

// round 13
// speedup vs baseline: 1.4706x; 1.4706x over previous
#include <cuda_runtime.h>
#include <cuda_bf16.h>

// Problem dims
#define B_   64
#define T_   96
#define F_   32
#define H_   128
#define HS4  512      // 4*H
#define NTH  512

// ---- shared memory layout (float offsets) ----
#define OFF_W1C    0        // 16384 f : w1 state rows bf16 [256][128] (enc/dec)
#define OFF_XDPRE  16384    // 6240 f  : decoder attn precompute bf16 [96][130] (65 uints/row)
                            //           encoder: xepre fp32 [32][136]
#define OFF_XM     22624    // 24576 f : decoder: XM deltas uint2[24][512] (paired rows)
                            //           encoder: xenc fp32 [96][129] @ +0, enc_k bf16 @ +12384
                            //           dec-pre: staged ad_w1 x-rows bf16 @ +12384
#define OFF_EKS    35008    // = OFF_XM + 12384 (enc_k bf16 during encoder)
#define OFF_XIN    47200    // 3072   : inputs[b] as [t][f]
#define OFF_RED4   50272    // 2048   : decoder B partials / encoder z / XM-stage tile
#define OFF_RED2   52320    // 1024   : encoder B partials 0,1
#define OFF_REDA   53344    // 1024   : a-partials 8x128 / e3[768]
#define OFF_ZS     54368    // 512    : decoder gate pre-activations / encoder B partial 2
#define OFF_MY     54880    // 512    : M row 128 (y coefficient)
#define OFF_BB     55392    // 512    : folded bias (dec) / enc_b cache (enc)
#define OFF_XMB    55904    // 512    : XM mean row (dec) / encoder B partial 3
#define OFF_HS     56416    // 256    : [h|s] / [d|c]
#define OFF_AW     56672    // 128
#define OFF_EW     56800    // 96
#define OFF_BETA   56896    // 96
#define OFF_XT     56992    // 32
#define OFF_CTX    57024    // 128
#define OFF_W2     57152    // 128
#define OFF_B1     57280    // 128
#define OFF_XSUM   57408    // 128
#define SMEM_F     57536
#define SMEM_BYTES (SMEM_F * 4)   // 230144 bytes

#define XE_S 129   // xenc fp32 row stride
#define XP_S 136   // xepre fp32 row stride (conflict-free with j=sub+8i mapping)
#define XD_U 65    // xdpre row stride in uints

#define BAR_A() asm volatile("bar.sync 1, 256;" ::: "memory")

// global scratch (static __device__ — no dynamic allocation)
__device__ float g_M[129 * 512];
__device__ float g_bb[512];
__device__ float g_xenc[B_ * T_ * H_];
__device__ uint4 g_enc_r_b4[8192];   // enc_r bf16 [128][512]
__device__ uint4 g_dec_r_b4[8192];   // dec_r bf16 [128][512]

// precise nonlinearities (LSTM cell only)
__device__ __forceinline__ float tanh_f(float x) {
    float e = __expf(2.0f * x);
    return 1.0f - __fdividef(2.0f, e + 1.0f);
}
__device__ __forceinline__ float sig_f(float x) {
    return __fdividef(1.0f, 1.0f + __expf(-x));
}
// fast tanh (attention only — softmax-damped)
__device__ __forceinline__ float tanh_a(float x) {
    float r;
    asm("tanh.approx.f32 %0, %1;" : "=f"(r) : "f"(x));
    return r;
}
__device__ __forceinline__ void fma4(float4& a, float s, const float4 w) {
    a.x = fmaf(s, w.x, a.x); a.y = fmaf(s, w.y, a.y);
    a.z = fmaf(s, w.z, a.z); a.w = fmaf(s, w.w, a.w);
}
// packed f32x2 helpers (FFMA2)
__device__ __forceinline__ unsigned long long pack2(float s) {
    unsigned long long r;
    asm("mov.b64 %0, {%1, %1};" : "=l"(r) : "f"(s));
    return r;
}
__device__ __forceinline__ void ffma2(unsigned long long& a, unsigned long long x,
                                      unsigned long long w) {
    asm("fma.rn.f32x2 %0, %1, %2, %0;" : "+l"(a) : "l"(x), "l"(w));
}
__device__ __forceinline__ float2 unpack2(unsigned long long a) {
    float2 f;
    asm("mov.b64 {%0, %1}, %2;" : "=f"(f.x), "=f"(f.y) : "l"(a));
    return f;
}
__device__ __forceinline__ float blo(unsigned u) { return __uint_as_float(u << 16); }
__device__ __forceinline__ float bhi(unsigned u) { return __uint_as_float(u & 0xffff0000u); }
// 8 bf16 (uint4) -> fp32 fma
__device__ __forceinline__ void fma_b8(float a[8], float s, uint4 w) {
    a[0] = fmaf(s, blo(w.x), a[0]); a[1] = fmaf(s, bhi(w.x), a[1]);
    a[2] = fmaf(s, blo(w.y), a[2]); a[3] = fmaf(s, bhi(w.y), a[3]);
    a[4] = fmaf(s, blo(w.z), a[4]); a[5] = fmaf(s, bhi(w.z), a[5]);
    a[6] = fmaf(s, blo(w.w), a[6]); a[7] = fmaf(s, bhi(w.w), a[7]);
}

extern __shared__ float sm[];

// ======  prep kernel: M = fc_w @ dec_k, folded bias, bf16 weight copies  ======
__global__ void __launch_bounds__(512, 1)
prep_kernel(const float* __restrict__ fc_w, const float* __restrict__ fc_b,
            const float* __restrict__ dec_k, const float* __restrict__ dec_b,
            const float* __restrict__ enc_r, const float* __restrict__ dec_r)
{
    int col = threadIdx.x;
    int r = blockIdx.x;
    if (r < 129) {
        float acc = 0.f;
        #pragma unroll 8
        for (int j = 0; j < 128; ++j)
            acc = fmaf(fc_w[r * 128 + j], dec_k[j * 512 + col], acc);
        g_M[r * 512 + col] = acc;
    } else if (r == 129) {
        float acc = dec_b[col];
        #pragma unroll 8
        for (int j = 0; j < 128; ++j)
            acc = fmaf(fc_b[j], dec_k[j * 512 + col], acc);
        g_bb[col] = acc;
    } else {
        int idx = (r - 130) * 512 + col;   // [0, 65536)
        const float* src; unsigned* dst; int i;
        if (idx < 32768) { src = enc_r; dst = (unsigned*)g_enc_r_b4; i = idx; }
        else             { src = dec_r; dst = (unsigned*)g_dec_r_b4; i = idx - 32768; }
        __nv_bfloat162 h = __floats2bfloat162_rn(src[2 * i], src[2 * i + 1]);
        dst[i] = *reinterpret_cast<unsigned*>(&h);
    }
}

// =====================  main kernel  =====================
__global__ void __launch_bounds__(NTH, 1)
darnn_kernel(const float* __restrict__ inputs,
             const float* __restrict__ enc_k,
             const float* __restrict__ enc_b,
             const float* __restrict__ ae_w1, const float* __restrict__ ae_b1,
             const float* __restrict__ ae_w2,
             const float* __restrict__ ad_w1, const float* __restrict__ ad_b1,
             const float* __restrict__ ad_w2,
             const float* __restrict__ ff_w, const float* __restrict__ ff_b,
             float* __restrict__ out)
{
    const int tid = threadIdx.x;
    const int b   = blockIdx.x;

    __nv_bfloat16* w1c = (__nv_bfloat16*)(sm + OFF_W1C);
    const uint2*   w1c_u2 = (const uint2*)(sm + OFF_W1C);
    unsigned*      xdpre_u = (unsigned*)(sm + OFF_XDPRE);
    float*    xepre = sm + OFF_XDPRE;           // encoder alias of xdpre region
    float*    xmreg = sm + OFF_XM;              // encoder: xenc fp32 at base
    __nv_bfloat16* eks = (__nv_bfloat16*)(sm + OFF_EKS);    // encoder: enc_k bf16
    __nv_bfloat16* w1x = (__nv_bfloat16*)(sm + OFF_XM + 12384);  // dec-pre staging
    const uint2*   w1x_u2 = (const uint2*)(sm + OFF_XM + 12384);
    unsigned* XM_u  = (unsigned*)(sm + OFF_XM); // decoder: paired bf16x2 deltas
    float* xin   = sm + OFF_XIN;
    float* red4  = sm + OFF_RED4;
    float* red2  = sm + OFF_RED2;
    float* redA  = sm + OFF_REDA;
    float* e3    = sm + OFF_REDA;               // decoder e-partials (aliases redA)
    float* zs    = sm + OFF_ZS;
    float* my    = sm + OFF_MY;
    float* bbs   = sm + OFF_BB;
    float* xmb   = sm + OFF_XMB;
    float* hs    = sm + OFF_HS;
    float* aw    = sm + OFF_AW;
    float* ew    = sm + OFF_EW;
    float* beta  = sm + OFF_BETA;
    float* xt    = sm + OFF_XT;
    float* ctx   = sm + OFF_CTX;
    float* w2c   = sm + OFF_W2;
    float* b1c   = sm + OFF_B1;
    float* xsum  = sm + OFF_XSUM;

    // ---------- Phase 0: stage inputs + encoder constants ----------
    for (int i = tid; i < T_ * F_; i += NTH) xin[i] = inputs[b * T_ * F_ + i];
    for (int i = tid; i < 256 * H_; i += NTH) w1c[i] = __float2bfloat16_rn(ae_w1[i]);
    for (int i = tid; i < F_ * HS4; i += NTH) eks[i] = __float2bfloat16_rn(enc_k[i]);
    if (tid < H_)   { w2c[tid] = ae_w2[tid]; b1c[tid] = ae_b1[tid]; }
    if (tid < 2*H_) hs[tid] = 0.0f;
    for (int i = tid; i < HS4; i += NTH) bbs[i] = enc_b[i];
    __syncthreads();

    // xe_pre[f][j] = sum_t x[t][f] * ae_w1[2H+t][j]  (one-time hoist)
    for (int slot = tid; slot < F_ * (H_ / 4); slot += NTH) {
        int f = slot >> 5, jq = slot & 31;
        float4 acc = make_float4(0.f, 0.f, 0.f, 0.f);
        #pragma unroll 4
        for (int t = 0; t < T_; ++t) {
            float xv = xin[t * F_ + f];
            float4 w = reinterpret_cast<const float4*>(ae_w1 + (256 + t) * H_)[jq];
            fma4(acc, xv, w);
        }
        float* dst = xepre + f * XP_S + jq * 4;
        dst[0] = acc.x; dst[1] = acc.y; dst[2] = acc.z; dst[3] = acc.w;
    }
    __syncthreads();

    // ---------- Phase 1: encoder (96 steps, overlapped groups) ----------
    for (int t = 0; t < T_; ++t) {
        if (tid < 256) {
            // Group A: a-partials [h|s]@w1 (bf16), 8 parts x 32 rows x 4 cols
            {
                int cg = tid & 31, part = tid >> 5;
                float a0 = 0.f, a1 = 0.f, a2 = 0.f, a3 = 0.f;
                int r0 = part * 32;
                #pragma unroll 8
                for (int r = r0; r < r0 + 32; ++r) {
                    float s = hs[r];
                    uint2 w = w1c_u2[r * 32 + cg];
                    a0 = fmaf(s, blo(w.x), a0); a1 = fmaf(s, bhi(w.x), a1);
                    a2 = fmaf(s, blo(w.y), a2); a3 = fmaf(s, bhi(w.y), a3);
                }
                reinterpret_cast<float4*>(redA + part * H_ + cg * 4)[0] =
                    make_float4(a0, a1, a2, a3);
            }
            BAR_A();
            if (tid < H_) {
                float acc = b1c[tid];
                #pragma unroll
                for (int p = 0; p < 8; ++p) acc += redA[p * H_ + tid];
                aw[tid] = acc;
            }
            BAR_A();
            // e[f] = sum_j tanh(xe_pre + a) * w2  (8 thr/f, interleaved j)
            {
                int f = tid >> 3, sub = tid & 7;
                float acc = 0.f;
                #pragma unroll
                for (int i = 0; i < 16; ++i) {
                    int j = sub + 8 * i;
                    acc += tanh_a(xepre[f * XP_S + j] + aw[j]) * w2c[j];
                }
                acc += __shfl_down_sync(0xffffffffu, acc, 4);
                acc += __shfl_down_sync(0xffffffffu, acc, 2);
                acc += __shfl_down_sync(0xffffffffu, acc, 1);
                if (sub == 0) ew[f] = acc;
            }
            BAR_A();
            // softmax over F=32 -> x_tilde
            if (tid < 32) {
                float v = ew[tid], m = v;
                #pragma unroll
                for (int o = 16; o; o >>= 1) m = fmaxf(m, __shfl_xor_sync(0xffffffffu, m, o));
                float p = __expf(v - m), s = p;
                #pragma unroll
                for (int o = 16; o; o >>= 1) s += __shfl_xor_sync(0xffffffffu, s, o);
                xt[tid] = __fdividef(p, s) * xin[t * F_ + tid];
            }
        } else {
            // Group B: zr = h @ enc_r (bf16), 4 parts x 32 rows x 8 cols, chunked
            int th = tid - 256;
            int colg = th & 63, part = th >> 6;
            int r0 = part * 32;
            float acc[8] = {0.f,0.f,0.f,0.f,0.f,0.f,0.f,0.f};
            #pragma unroll
            for (int c = 0; c < 4; ++c) {
                uint4 wv[8];
                #pragma unroll
                for (int k = 0; k < 8; ++k)
                    wv[k] = g_enc_r_b4[(r0 + c * 8 + k) * 64 + colg];
                #pragma unroll
                for (int k = 0; k < 8; ++k)
                    fma_b8(acc, hs[r0 + c * 8 + k], wv[k]);
            }
            float* dst = (part == 0) ? red2 : (part == 1) ? (red2 + 512)
                       : (part == 2) ? zs : xmb;
            reinterpret_cast<float4*>(dst + colg * 8)[0] =
                make_float4(acc[0], acc[1], acc[2], acc[3]);
            reinterpret_cast<float4*>(dst + colg * 8 + 4)[0] =
                make_float4(acc[4], acc[5], acc[6], acc[7]);
        }
        __syncthreads();

        // z-combine (512 thr, 1 col): bias + 4 zr parts + x_tilde @ enc_k (smem bf16)
        {
            int col = tid;
            float z = bbs[col] + red2[col] + red2[512 + col] + zs[col] + xmb[col];
            #pragma unroll 8
            for (int r = 0; r < 32; ++r)
                z = fmaf(xt[r], __bfloat162float(eks[r * HS4 + col]), z);
            red4[col] = z;
        }
        __syncthreads();

        // LSTM cell
        if (tid < H_) {
            int j = tid;
            float ig = sig_f(red4[j]), fg = sig_f(red4[H_ + j]);
            float gg = tanh_f(red4[2 * H_ + j]), og = sig_f(red4[3 * H_ + j]);
            float c = fg * hs[H_ + j] + ig * gg;
            float h = og * tanh_f(c);
            hs[j] = h; hs[H_ + j] = c;
            xmreg[t * XE_S + j] = h;
            g_xenc[(b * T_ + t) * H_ + j] = h;
        }
        __syncthreads();
    }

    // ---------- Phase 2: decoder precomputes ----------
    for (int i = tid; i < 256 * H_; i += NTH) w1c[i] = __float2bfloat16_rn(ad_w1[i]);
    for (int i = tid; i < H_ * H_; i += NTH)
        w1x[i] = __float2bfloat16_rn(ad_w1[256 * H_ + i]);
    if (tid < H_)   { w2c[tid] = ad_w2[tid]; b1c[tid] = ad_b1[tid]; }
    if (tid < 2*H_) hs[tid] = 0.0f;
    if (tid < 512)  { bbs[tid] = g_bb[tid]; my[tid] = g_M[128 * 512 + tid]; }
    __syncthreads();

    // xd_pre[tt][j] -> bf16 [96][130]
    for (int slot = tid; slot < T_ * (H_ / 4); slot += NTH) {
        int tt = slot >> 5, jq = slot & 31;
        float a0 = 0.f, a1 = 0.f, a2 = 0.f, a3 = 0.f;
        #pragma unroll 8
        for (int k = 0; k < H_; ++k) {
            float xv = xmreg[tt * XE_S + k];
            uint2 w = w1x_u2[k * 32 + jq];
            a0 = fmaf(xv, blo(w.x), a0); a1 = fmaf(xv, bhi(w.x), a1);
            a2 = fmaf(xv, blo(w.y), a2); a3 = fmaf(xv, bhi(w.y), a3);
        }
        __nv_bfloat162 h0 = __floats2bfloat162_rn(a0, a1);
        __nv_bfloat162 h1 = __floats2bfloat162_rn(a2, a3);
        xdpre_u[tt * XD_U + jq * 2]     = *reinterpret_cast<unsigned*>(&h0);
        xdpre_u[tt * XD_U + jq * 2 + 1] = *reinterpret_cast<unsigned*>(&h1);
    }
    // xsum[k] = sum_tt xenc[tt][k]
    if (tid < H_) {
        float acc = 0.f;
        #pragma unroll 8
        for (int tt = 0; tt < T_; ++tt) acc += xmreg[tt * XE_S + tid];
        xsum[tid] = acc;
    }
    __syncthreads();

    // XMbar[col] = (1/96) * sum_k xsum[k] * M[k][col]
    {
        int col = tid;
        float acc = 0.f;
        #pragma unroll 8
        for (int k = 0; k < H_; ++k)
            acc = fmaf(xsum[k], g_M[k * 512 + col], acc);
        xmb[col] = acc * (1.0f / 96.0f);
    }
    __syncthreads();

    // XM passes, reverse order p=5..0 (writes stay ahead of later xenc reads)
    // Paired layout: uint2 rows q2=0..23 (row stride 1024 uints); row q2 covers
    // tt 4*q2..4*q2+3.
    for (int p = 5; p >= 0; --p) {
        for (int idx = tid; idx < 2048; idx += NTH) {
            int k = idx >> 4, u = idx & 15;
            red4[idx] = xmreg[(16 * p + u) * XE_S + k];
        }
        __syncthreads();
        {
            int col = tid;
            unsigned long long acc2[8];
            #pragma unroll
            for (int j = 0; j < 8; ++j) acc2[j] = 0ull;
            const float* Mp = g_M + col;
            const ulonglong2* Tb = (const ulonglong2*)red4;
            #pragma unroll 4
            for (int k = 0; k < 128; ++k) {
                unsigned long long mm = pack2(Mp[k * 512]);
                ulonglong2 t0 = Tb[k * 4 + 0];
                ulonglong2 t1 = Tb[k * 4 + 1];
                ulonglong2 t2 = Tb[k * 4 + 2];
                ulonglong2 t3 = Tb[k * 4 + 3];
                ffma2(acc2[0], t0.x, mm); ffma2(acc2[1], t0.y, mm);
                ffma2(acc2[2], t1.x, mm); ffma2(acc2[3], t1.y, mm);
                ffma2(acc2[4], t2.x, mm); ffma2(acc2[5], t2.y, mm);
                ffma2(acc2[6], t3.x, mm); ffma2(acc2[7], t3.y, mm);
            }
            float xb = xmb[col];
            #pragma unroll
            for (int j2 = 0; j2 < 4; ++j2) {
                float2 fa = unpack2(acc2[2 * j2]);
                float2 fb = unpack2(acc2[2 * j2 + 1]);
                __nv_bfloat162 ha = __floats2bfloat162_rn(fa.x - xb, fa.y - xb);
                __nv_bfloat162 hb = __floats2bfloat162_rn(fb.x - xb, fb.y - xb);
                uint2 v;
                v.x = *reinterpret_cast<unsigned*>(&ha);
                v.y = *reinterpret_cast<unsigned*>(&hb);
                *reinterpret_cast<uint2*>(XM_u + (4 * p + j2) * 1024 + col * 2) = v;
            }
        }
        __syncthreads();
    }

    // ---------- Phase 3: decoder (96 steps) ----------
    for (int t = 0; t < T_; ++t) {
        if (tid < 256) {
            // ===== Group A: full attention chain (overlaps B) =====
            {
                int cg = tid & 31, part = tid >> 5;
                float a0 = 0.f, a1 = 0.f, a2 = 0.f, a3 = 0.f;
                int r0 = part * 32;
                #pragma unroll 8
                for (int r = r0; r < r0 + 32; ++r) {
                    float s = hs[r];
                    uint2 w = w1c_u2[r * 32 + cg];
                    a0 = fmaf(s, blo(w.x), a0); a1 = fmaf(s, bhi(w.x), a1);
                    a2 = fmaf(s, blo(w.y), a2); a3 = fmaf(s, bhi(w.y), a3);
                }
                reinterpret_cast<float4*>(redA + part * H_ + cg * 4)[0] =
                    make_float4(a0, a1, a2, a3);
            }
            BAR_A();
            if (tid < H_) {
                float acc = b1c[tid];
                #pragma unroll
                for (int p = 0; p < 8; ++p) acc += redA[p * H_ + tid];
                aw[tid] = acc;
            }
            BAR_A();
            // e-phase on 256 threads: 3 units x 16 tanh (unit = jb*96+tt)
            {
                #pragma unroll
                for (int k2 = 0; k2 < 3; ++k2) {
                    int unit = tid + 256 * k2;
                    int tt = unit % 96, jb = unit / 96;
                    const unsigned* row = xdpre_u + tt * XD_U + jb * 8;
                    int j0 = jb * 16;
                    float acc = 0.f;
                    #pragma unroll
                    for (int i = 0; i < 8; ++i) {
                        unsigned u = row[i];
                        int j = j0 + 2 * i;
                        acc += tanh_a(blo(u) + aw[j])     * w2c[j];
                        acc += tanh_a(bhi(u) + aw[j + 1]) * w2c[j + 1];
                    }
                    e3[unit] = acc;
                }
            }
            BAR_A();
            // softmax over T=96 (sum 8 jb-partials per tt)
            if (tid < 32) {
                float v0 = 0.f, v1 = 0.f, v2 = 0.f;
                #pragma unroll
                for (int jb = 0; jb < 8; ++jb) {
                    v0 += e3[jb * 96 + tid];
                    v1 += e3[jb * 96 + tid + 32];
                    v2 += e3[jb * 96 + tid + 64];
                }
                float m = fmaxf(v0, fmaxf(v1, v2));
                #pragma unroll
                for (int o = 16; o; o >>= 1) m = fmaxf(m, __shfl_xor_sync(0xffffffffu, m, o));
                float p0 = __expf(v0 - m), p1 = __expf(v1 - m), p2 = __expf(v2 - m);
                float s = p0 + p1 + p2;
                #pragma unroll
                for (int o = 16; o; o >>= 1) s += __shfl_xor_sync(0xffffffffu, s, o);
                float inv = __fdividef(1.0f, s);
                beta[tid] = p0 * inv; beta[tid + 32] = p1 * inv; beta[tid + 64] = p2 * inv;
            }
        } else {
            // ===== Group B: zr = d @ dec_r (bf16), 4 parts x 32 rows, chunked =====
            int th = tid - 256;
            int colg = th & 63, part = th >> 6;
            int r0 = part * 32;
            float acc[8] = {0.f,0.f,0.f,0.f,0.f,0.f,0.f,0.f};
            #pragma unroll
            for (int c = 0; c < 4; ++c) {
                uint4 wv[8];
                #pragma unroll
                for (int k = 0; k < 8; ++k)
                    wv[k] = g_dec_r_b4[(r0 + c * 8 + k) * 64 + colg];
                #pragma unroll
                for (int k = 0; k < 8; ++k)
                    fma_b8(acc, hs[r0 + c * 8 + k], wv[k]);
            }
            float* dst = red4 + part * HS4;
            reinterpret_cast<float4*>(dst + colg * 8)[0] =
                make_float4(acc[0], acc[1], acc[2], acc[3]);
            reinterpret_cast<float4*>(dst + colg * 8 + 4)[0] =
                make_float4(acc[4], acc[5], acc[6], acc[7]);
        }
        __syncthreads();

        // z[col] = bb + sum(zr parts) + y*my + XMbar + sum_q2 beta4·XMdelta
        {
            int col = tid;
            float z = bbs[col] + xmb[col];
            z += red4[col] + red4[512 + col] + red4[1024 + col] + red4[1536 + col];
            z = fmaf(xin[t * F_ + (F_ - 1)], my[col], z);
            const uint2* xr = reinterpret_cast<const uint2*>(XM_u) + col;
            const float4* b4 = reinterpret_cast<const float4*>(beta);
            #pragma unroll 8
            for (int q2 = 0; q2 < 24; ++q2) {
                uint2 u = xr[q2 * 512];
                float4 bq = b4[q2];
                z = fmaf(bq.x, blo(u.x), z);
                z = fmaf(bq.y, bhi(u.x), z);
                z = fmaf(bq.z, blo(u.y), z);
                z = fmaf(bq.w, bhi(u.y), z);
            }
            zs[col] = z;
        }
        __syncthreads();

        // LSTM cell
        if (tid < H_) {
            int j = tid;
            float ig = sig_f(zs[j]), fg = sig_f(zs[H_ + j]);
            float gg = tanh_f(zs[2 * H_ + j]), og = sig_f(zs[3 * H_ + j]);
            float c = fg * hs[H_ + j] + ig * gg;
            float d = og * tanh_f(c);
            hs[j] = d; hs[H_ + j] = c;
        }
        __syncthreads();
    }

    // ---------- Phase 4: final ctx + output head ----------
    if (tid < H_) {
        float acc = 0.f;
        const float* xg = g_xenc + b * T_ * H_ + tid;
        #pragma unroll 8
        for (int tt = 0; tt < T_; ++tt) acc += beta[tt] * xg[tt * H_];
        ctx[tid] = acc;
    }
    __syncthreads();
    if (tid < F_) {
        float acc = ff_b[tid];
        #pragma unroll 4
        for (int k = 0; k < H_; ++k) acc += hs[k] * ff_w[k * F_ + tid];
        #pragma unroll 4
        for (int k = 0; k < H_; ++k) acc += ctx[k] * ff_w[(H_ + k) * F_ + tid];
        out[b * F_ + tid] = acc;
    }
}

extern "C" void kernel_launch(void* const* d_in, const int* in_sizes, int n_in,
                              void* d_out, int out_size) {
    const float* inputs = (const float*)d_in[0];
    const float* enc_k  = (const float*)d_in[1];
    const float* enc_r  = (const float*)d_in[2];
    const float* enc_b  = (const float*)d_in[3];
    const float* ae_w1  = (const float*)d_in[4];
    const float* ae_b1  = (const float*)d_in[5];
    const float* ae_w2  = (const float*)d_in[6];
    const float* dec_k  = (const float*)d_in[8];
    const float* dec_r  = (const float*)d_in[9];
    const float* dec_b  = (const float*)d_in[10];
    const float* ad_w1  = (const float*)d_in[11];
    const float* ad_b1  = (const float*)d_in[12];
    const float* ad_w2  = (const float*)d_in[13];
    const float* fc_w   = (const float*)d_in[15];
    const float* fc_b   = (const float*)d_in[16];
    const float* ff_w   = (const float*)d_in[17];
    const float* ff_b   = (const float*)d_in[18];
    float* out = (float*)d_out;

    prep_kernel<<<258, 512>>>(fc_w, fc_b, dec_k, dec_b, enc_r, dec_r);

    cudaFuncSetAttribute(darnn_kernel, cudaFuncAttributeMaxDynamicSharedMemorySize, SMEM_BYTES);
    darnn_kernel<<<B_, NTH, SMEM_BYTES>>>(inputs, enc_k, enc_b,
                                          ae_w1, ae_b1, ae_w2,
                                          ad_w1, ad_b1, ad_w2,
                                          ff_w, ff_b, out);
}